// round 1
// baseline (speedup 1.0000x reference)
#include <cuda_runtime.h>

// GCNLayer_EdgeCat: fused GNN layer on GB300.
//   m    = ReLU([nf[src], ef, nf[dst]] @ We + be)         [E,H]
//   h    = segment_mean(m, dst)                            [N,H]
//   out1 = ReLU([nf, h] @ Wn + bn) + nf                    [N,H]
//   out2 = m + ef                                          [E,H]
//
// Weight-split algebra: We = [We1; We2; We3] (row blocks), Wn = [Wn1; Wn2].
//   A  = nf @ We1 + be,  C = nf @ We3,  An = nf @ Wn1 + bn   (node precompute)
//   m  = ReLU(A[src] + ef @ We2 + C[dst])                    (edge kernel)
//   out1 = ReLU(An + (sum/cnt) @ Wn2) + nf                   (node update)

#define H        128
#define H4       32          // H / 4 (float4 granularity)
#define NNODE    50000
#define NEDGE    800000
#define BT       64          // rows (edges/nodes) per block tile
#define NTHREADS 256

// Static device scratch (allocation is forbidden at runtime).
__device__ float g_A  [(size_t)NNODE * H];
__device__ float g_C  [(size_t)NNODE * H];
__device__ float g_An [(size_t)NNODE * H];
__device__ float g_sum[(size_t)NNODE * H];
__device__ float g_cnt[NNODE];

__device__ __forceinline__ void red_add_v4(float* p, float4 v) {
    asm volatile("red.global.add.v4.f32 [%0], {%1, %2, %3, %4};"
                 :: "l"(p), "f"(v.x), "f"(v.y), "f"(v.z), "f"(v.w) : "memory");
}

// Register-tiled [BT x H] = [BT x H] @ [H x H] micro-GEMM.
// Thread layout: cg = tid&31 selects 4 output cols (cg*4..+3), rg = tid>>5
// selects 8 rows (rg*8..+7). A-side reads are warp-broadcast (all lanes in a
// warp share rg); W-side float4 reads are quarter-warp conflict-free.
__device__ __forceinline__ void mm_tile(const float4* __restrict__ sA4,
                                        const float4* __restrict__ sW4,
                                        int r0, int cg, float4 acc[8]) {
#pragma unroll 4
    for (int k = 0; k < H; k += 4) {
        float4 w0 = sW4[(k + 0) * H4 + cg];
        float4 w1 = sW4[(k + 1) * H4 + cg];
        float4 w2 = sW4[(k + 2) * H4 + cg];
        float4 w3 = sW4[(k + 3) * H4 + cg];
#pragma unroll
        for (int i = 0; i < 8; i++) {
            float4 a = sA4[(r0 + i) * H4 + (k >> 2)];
            acc[i].x = fmaf(a.x, w0.x, fmaf(a.y, w1.x, fmaf(a.z, w2.x, fmaf(a.w, w3.x, acc[i].x))));
            acc[i].y = fmaf(a.x, w0.y, fmaf(a.y, w1.y, fmaf(a.z, w2.y, fmaf(a.w, w3.y, acc[i].y))));
            acc[i].z = fmaf(a.x, w0.z, fmaf(a.y, w1.z, fmaf(a.z, w2.z, fmaf(a.w, w3.z, acc[i].z))));
            acc[i].w = fmaf(a.x, w0.w, fmaf(a.y, w1.w, fmaf(a.z, w2.w, fmaf(a.w, w3.w, acc[i].w))));
        }
    }
}

__global__ void k_zero() {
    int i = blockIdx.x * blockDim.x + threadIdx.x;
    int stride = gridDim.x * blockDim.x;
    float4 z = make_float4(0.f, 0.f, 0.f, 0.f);
    for (int j = i; j < NNODE * H4; j += stride) ((float4*)g_sum)[j] = z;
    for (int j = i; j < NNODE; j += stride) g_cnt[j] = 0.f;
}

// ---- Node precompute: A = nf@We1+be, C = nf@We3, An = nf@Wn1+bn ----
__global__ __launch_bounds__(NTHREADS)
void k_node_pre(const float* __restrict__ nf,
                const float* __restrict__ We, const float* __restrict__ be,
                const float* __restrict__ Wn, const float* __restrict__ bn) {
    extern __shared__ float smem[];
    float4* sNF4 = (float4*)smem;                 // BT x H  (32 KB)
    float4* sW4  = (float4*)(smem + BT * H);      // H  x H  (64 KB)
    int t  = threadIdx.x;
    int cg = t & 31, rg = t >> 5, r0 = rg * 8;
    int nb = blockIdx.x * BT;

    for (int idx = t; idx < BT * H4; idx += NTHREADS) {
        int n = nb + (idx >> 5);
        sNF4[idx] = (n < NNODE) ? ((const float4*)nf)[(size_t)n * H4 + (idx & 31)]
                                : make_float4(0.f, 0.f, 0.f, 0.f);
    }

    const float* Wsrc[3] = { We, We + 2 * H * H, Wn };
    float*       Odst[3] = { g_A, g_C, g_An };
    const float* bsrc[3] = { be, (const float*)0, bn };

    for (int ph = 0; ph < 3; ph++) {
        __syncthreads();
        for (int idx = t; idx < H * H4; idx += NTHREADS)
            sW4[idx] = ((const float4*)Wsrc[ph])[idx];
        __syncthreads();

        float4 acc[8];
#pragma unroll
        for (int i = 0; i < 8; i++) acc[i] = make_float4(0.f, 0.f, 0.f, 0.f);
        mm_tile(sNF4, sW4, r0, cg, acc);

        float4 b = make_float4(0.f, 0.f, 0.f, 0.f);
        if (bsrc[ph]) b = ((const float4*)bsrc[ph])[cg];
#pragma unroll
        for (int i = 0; i < 8; i++) {
            int n = nb + r0 + i;
            if (n < NNODE) {
                float4 v;
                v.x = acc[i].x + b.x; v.y = acc[i].y + b.y;
                v.z = acc[i].z + b.z; v.w = acc[i].w + b.w;
                ((float4*)Odst[ph])[(size_t)n * H4 + cg] = v;
            }
        }
    }
}

// ---- Edge kernel: m = ReLU(A[src] + ef@We2 + C[dst]); out2 = m + ef;
//      scatter-add m into g_sum[dst], count into g_cnt[dst]. ----
__global__ __launch_bounds__(NTHREADS)
void k_edge(const float* __restrict__ ef,
            const int* __restrict__ src, const int* __restrict__ dst,
            const float* __restrict__ We, float* __restrict__ out2) {
    extern __shared__ float smem[];
    float4* sA4 = (float4*)smem;                  // BT x H (ef tile)
    float4* sW4 = (float4*)(smem + BT * H);       // H  x H (We2)
    int* s_src = (int*)(smem + BT * H + H * H);
    int* s_dst = s_src + BT;
    int t  = threadIdx.x;
    int cg = t & 31, rg = t >> 5, r0 = rg * 8;
    int eb = blockIdx.x * BT;

    if (t < BT) { s_src[t] = src[eb + t]; s_dst[t] = dst[eb + t]; }
    for (int idx = t; idx < BT * H4; idx += NTHREADS)
        sA4[idx] = ((const float4*)ef)[(size_t)eb * H4 + idx];
    for (int idx = t; idx < H * H4; idx += NTHREADS)
        sW4[idx] = ((const float4*)(We + H * H))[idx];   // We2 rows 128..255
    __syncthreads();

    float4 acc[8];
#pragma unroll
    for (int i = 0; i < 8; i++) acc[i] = make_float4(0.f, 0.f, 0.f, 0.f);
    mm_tile(sA4, sW4, r0, cg, acc);

#pragma unroll
    for (int i = 0; i < 8; i++) {
        int e  = r0 + i;
        int ge = eb + e;
        int s = s_src[e], d = s_dst[e];
        float4 a = ((const float4*)g_A)[(size_t)s * H4 + cg];
        float4 c = ((const float4*)g_C)[(size_t)d * H4 + cg];
        float4 m;
        m.x = fmaxf(acc[i].x + a.x + c.x, 0.f);
        m.y = fmaxf(acc[i].y + a.y + c.y, 0.f);
        m.z = fmaxf(acc[i].z + a.z + c.z, 0.f);
        m.w = fmaxf(acc[i].w + a.w + c.w, 0.f);
        float4 efv = sA4[e * H4 + cg];            // exact fp32 ef, still in smem
        float4 o;
        o.x = m.x + efv.x; o.y = m.y + efv.y;
        o.z = m.z + efv.z; o.w = m.w + efv.w;
        ((float4*)out2)[(size_t)ge * H4 + cg] = o;
        red_add_v4(&g_sum[(size_t)d * H + cg * 4], m);
        if (cg == 0) atomicAdd(&g_cnt[d], 1.0f);
    }
}

// ---- Node update: out1 = ReLU(An + (sum/max(cnt,1)) @ Wn2) + nf ----
__global__ __launch_bounds__(NTHREADS)
void k_node_upd(const float* __restrict__ nf,
                const float* __restrict__ Wn, float* __restrict__ out1) {
    extern __shared__ float smem[];
    float4* sH4 = (float4*)smem;                  // BT x H (mean messages)
    float4* sW4 = (float4*)(smem + BT * H);       // H  x H (Wn2)
    int t  = threadIdx.x;
    int cg = t & 31, rg = t >> 5, r0 = rg * 8;
    int nb = blockIdx.x * BT;

    for (int idx = t; idx < BT * H4; idx += NTHREADS) {
        int n = nb + (idx >> 5);
        float4 v = make_float4(0.f, 0.f, 0.f, 0.f);
        if (n < NNODE) {
            v = ((const float4*)g_sum)[(size_t)n * H4 + (idx & 31)];
            float inv = 1.0f / fmaxf(g_cnt[n], 1.0f);
            v.x *= inv; v.y *= inv; v.z *= inv; v.w *= inv;
        }
        sH4[idx] = v;
    }
    for (int idx = t; idx < H * H4; idx += NTHREADS)
        sW4[idx] = ((const float4*)(Wn + H * H))[idx];   // Wn2 rows 128..255
    __syncthreads();

    float4 acc[8];
#pragma unroll
    for (int i = 0; i < 8; i++) acc[i] = make_float4(0.f, 0.f, 0.f, 0.f);
    mm_tile(sH4, sW4, r0, cg, acc);

#pragma unroll
    for (int i = 0; i < 8; i++) {
        int n = nb + r0 + i;
        if (n < NNODE) {
            float4 an = ((const float4*)g_An)[(size_t)n * H4 + cg];
            float4 nv = ((const float4*)nf)[(size_t)n * H4 + cg];
            float4 o;
            o.x = fmaxf(acc[i].x + an.x, 0.f) + nv.x;
            o.y = fmaxf(acc[i].y + an.y, 0.f) + nv.y;
            o.z = fmaxf(acc[i].z + an.z, 0.f) + nv.z;
            o.w = fmaxf(acc[i].w + an.w, 0.f) + nv.w;
            ((float4*)out1)[(size_t)n * H4 + cg] = o;
        }
    }
}

extern "C" void kernel_launch(void* const* d_in, const int* in_sizes, int n_in,
                              void* d_out, int out_size) {
    const float* nf = (const float*)d_in[0];
    const float* ef = (const float*)d_in[1];
    const int*   src = (const int*)d_in[2];
    const int*   dst = (const int*)d_in[3];
    const float* We = (const float*)d_in[4];
    const float* be = (const float*)d_in[5];
    const float* Wn = (const float*)d_in[6];
    const float* bn = (const float*)d_in[7];
    float* out1 = (float*)d_out;                       // [N,H]  h_out + nf
    float* out2 = out1 + (size_t)NNODE * H;            // [E,H]  m + ef

    const int smem_mm   = (BT * H + H * H) * (int)sizeof(float);     // 96 KB
    const int smem_edge = smem_mm + 2 * BT * (int)sizeof(int);
    // Idempotent; >48KB dynamic smem needs the opt-in. Errors ignored on
    // purpose: attribute persists from the (non-captured) correctness call.
    cudaFuncSetAttribute(k_node_pre, cudaFuncAttributeMaxDynamicSharedMemorySize, smem_mm);
    cudaFuncSetAttribute(k_edge,     cudaFuncAttributeMaxDynamicSharedMemorySize, smem_edge);
    cudaFuncSetAttribute(k_node_upd, cudaFuncAttributeMaxDynamicSharedMemorySize, smem_mm);

    k_zero<<<400, 256>>>();
    k_node_pre<<<(NNODE + BT - 1) / BT, NTHREADS, smem_mm>>>(nf, We, be, Wn, bn);
    k_edge<<<NEDGE / BT, NTHREADS, smem_edge>>>(ef, src, dst, We, out2);
    k_node_upd<<<(NNODE + BT - 1) / BT, NTHREADS, smem_mm>>>(nf, Wn, out1);
}